// round 2
// baseline (speedup 1.0000x reference)
#include <cuda_runtime.h>
#include <math.h>

// LSTM cell, fused: z[g] = X @ Wx[g]^T + h0 @ Wh[g]^T + bx[g] + bh[g]
// Shapes: B=32768, E=H=512. One GEMM view: M=B, N=4H, K=E+H=1024,
// both operands K-contiguous (NT). Epilogue fused per (b,h) across 4 gates.

#define B_DIM 32768
#define K_DIM 512     // E == H == 512 -> identical strides for both K-segments
#define H_DIM 512

#define BM 128        // batch rows per CTA
#define BH 32         // h columns per CTA (x4 gates)
#define BK 16         // K step
#define TM 8          // rows per thread
#define TH 2          // h cols per thread
#define THREADS 256   // 16 (h) x 16 (m)

__global__ __launch_bounds__(THREADS, 2)
void lstm_fused_kernel(const float* __restrict__ x,
                       const float* __restrict__ h0,
                       const float* __restrict__ c0,
                       const float* __restrict__ Wx,
                       const float* __restrict__ bx,
                       const float* __restrict__ Wh,
                       const float* __restrict__ bh,
                       float* __restrict__ out)
{
    __shared__ float As[BK][BM];        // A tile, k-major (transposed on store)
    __shared__ float Ws[4][BK][BH];     // weight tiles per gate, k-major

    const int tid  = threadIdx.x;
    const int tx   = tid & 15;          // h-group 0..15
    const int ty   = tid >> 4;          // m-group 0..15
    const int hblk = blockIdx.x * BH;
    const int mblk = blockIdx.y * BM;
    const int m0   = ty * TM;
    const int hh0  = tx * TH;

    float acc[4][TM][TH];
    #pragma unroll
    for (int g = 0; g < 4; ++g)
        #pragma unroll
        for (int i = 0; i < TM; ++i)
            #pragma unroll
            for (int j = 0; j < TH; ++j)
                acc[g][i][j] = 0.0f;

    // 64 K-tiles of 16: tiles [0,32) consume (x, Wx); [32,64) consume (h0, Wh).
    for (int kt = 0; kt < 64; ++kt) {
        const float* Aptr = (kt < 32) ? x  : h0;
        const float* Wptr = (kt < 32) ? Wx : Wh;
        const int kg = (kt & 31) * BK;

        // ---- load A tile: 128 rows x 16 k, float4, store transposed ----
        #pragma unroll
        for (int j = 0; j < 2; ++j) {
            int idx = tid + j * 256;              // 0..511
            int row = idx >> 2;
            int kc  = (idx & 3) * 4;
            float4 v = *(const float4*)(Aptr + (size_t)(mblk + row) * K_DIM + kg + kc);
            As[kc + 0][row] = v.x;
            As[kc + 1][row] = v.y;
            As[kc + 2][row] = v.z;
            As[kc + 3][row] = v.w;
        }
        // ---- load W tiles: 4 gates x 32 h x 16 k ----
        #pragma unroll
        for (int j = 0; j < 2; ++j) {
            int idx = tid + j * 256;              // 0..511
            int g   = idx >> 7;
            int r   = idx & 127;
            int wh  = r >> 2;
            int kc  = (r & 3) * 4;
            float4 v = *(const float4*)(Wptr + ((size_t)g * H_DIM + hblk + wh) * K_DIM + kg + kc);
            Ws[g][kc + 0][wh] = v.x;
            Ws[g][kc + 1][wh] = v.y;
            Ws[g][kc + 2][wh] = v.z;
            Ws[g][kc + 3][wh] = v.w;
        }
        __syncthreads();

        // ---- inner product ----
        #pragma unroll
        for (int kk = 0; kk < BK; ++kk) {
            float a[TM];
            float4 a0 = *(const float4*)&As[kk][m0];
            float4 a1 = *(const float4*)&As[kk][m0 + 4];
            a[0] = a0.x; a[1] = a0.y; a[2] = a0.z; a[3] = a0.w;
            a[4] = a1.x; a[5] = a1.y; a[6] = a1.z; a[7] = a1.w;
            #pragma unroll
            for (int g = 0; g < 4; ++g) {
                float2 w = *(const float2*)&Ws[g][kk][hh0];
                #pragma unroll
                for (int i = 0; i < TM; ++i) {
                    acc[g][i][0] = fmaf(a[i], w.x, acc[g][i][0]);
                    acc[g][i][1] = fmaf(a[i], w.y, acc[g][i][1]);
                }
            }
        }
        __syncthreads();
    }

    // ---- fused LSTM epilogue ----
    float bsum[4][TH];
    #pragma unroll
    for (int g = 0; g < 4; ++g)
        #pragma unroll
        for (int j = 0; j < TH; ++j) {
            int h = hblk + hh0 + j;
            bsum[g][j] = bx[g * H_DIM + h] + bh[g * H_DIM + h];
        }

    #pragma unroll
    for (int i = 0; i < TM; ++i) {
        const size_t b = (size_t)(mblk + m0 + i);
        #pragma unroll
        for (int j = 0; j < TH; ++j) {
            const int h = hblk + hh0 + j;
            float zi = acc[0][i][j] + bsum[0][j];
            float zf = acc[1][i][j] + bsum[1][j];
            float zo = acc[2][i][j] + bsum[2][j];
            float zg = acc[3][i][j] + bsum[3][j];
            float ig = 1.0f / (1.0f + expf(-zi));
            float fg = 1.0f / (1.0f + expf(-zf));
            float og = 1.0f / (1.0f + expf(-zo));
            float gg = tanhf(zg);
            float cv = fg * c0[b * H_DIM + h] + ig * gg;
            float hv = og * tanhf(cv);
            out[b * H_DIM + h] = hv;                                  // h1
            out[(size_t)B_DIM * H_DIM + b * H_DIM + h] = cv;          // c1
        }
    }
}

extern "C" void kernel_launch(void* const* d_in, const int* in_sizes, int n_in,
                              void* d_out, int out_size)
{
    const float* x  = (const float*)d_in[0];
    const float* h0 = (const float*)d_in[1];
    const float* c0 = (const float*)d_in[2];
    const float* Wx = (const float*)d_in[3];
    const float* bx = (const float*)d_in[4];
    const float* Wh = (const float*)d_in[5];
    const float* bh = (const float*)d_in[6];
    float* out = (float*)d_out;

    dim3 grid(H_DIM / BH, B_DIM / BM);   // (16, 256)
    lstm_fused_kernel<<<grid, THREADS>>>(x, h0, c0, Wx, bx, Wh, bh, out);
}

// round 12
// speedup vs baseline: 3.4573x; 3.4573x over previous
#include <cuda_runtime.h>
#include <cstdint>
#include <math.h>

// LSTM cell via Ampere-style mma.sync tf32 (assembles on plain sm_103 target).
// GEMM view: Z[M=32768, N=2048] = A[M,1024] * W[2048,1024]^T (NT, K-major both).
// K chunks [0,16) use (x, Wx); [16,32) use (h0, Wh).
// CTA tile: 128 (M) x 128 (N = 4 gates x 32 h), BK=32, 3-stage cp.async pipeline.
// Warp (8 total): 4 (M) x 2 (H). Warp tile: 32 (M) x 16 (h) x 4 gates
//   = 2 m16 x 8 n8 mma tiles per k8 step. Gate fusion happens in registers.

#define B_DIM 32768
#define K_DIM 512
#define H_DIM 512

#define BM 128
#define BH 32
#define BK 32
#define STAGES 3
#define THREADS 256
#define NCHUNKS 32

#define ROW_BYTES 128                         // 32 floats per K-major row
#define A_OFF 0
#define B_OFF (BM * ROW_BYTES)                // 16 KB
#define STAGE_BYTES (2 * BM * ROW_BYTES)      // 32 KB
#define SMEM_DYN (STAGES * STAGE_BYTES)       // 96 KB

__device__ __forceinline__ uint32_t s2u(const void* p) {
    uint32_t a;
    asm("{ .reg .u64 t; cvta.to.shared.u64 t, %1; cvt.u32.u64 %0, t; }"
        : "=r"(a) : "l"(p));
    return a;
}

__device__ __forceinline__ uint32_t f2tf32(float f) {
    uint32_t u;
    asm("cvt.rna.tf32.f32 %0, %1;" : "=r"(u) : "f"(f));
    return u;
}

__device__ __forceinline__ void mma_tf32(float* c, const uint32_t* a, const uint32_t* b) {
    asm volatile(
        "mma.sync.aligned.m16n8k8.row.col.f32.tf32.tf32.f32 "
        "{%0,%1,%2,%3}, {%4,%5,%6,%7}, {%8,%9}, {%0,%1,%2,%3};"
        : "+f"(c[0]), "+f"(c[1]), "+f"(c[2]), "+f"(c[3])
        : "r"(a[0]), "r"(a[1]), "r"(a[2]), "r"(a[3]), "r"(b[0]), "r"(b[1]));
}

#define CP16(saddr, gaddr) \
    asm volatile("cp.async.cg.shared.global [%0], [%1], 16;" :: "r"(saddr), "l"(gaddr))
#define CP_COMMIT() asm volatile("cp.async.commit_group;" ::: "memory")
#define CP_WAIT2()  asm volatile("cp.async.wait_group 2;" ::: "memory")

// smem element address: row-major [row][32 floats], 16B segments XOR-swizzled by row
#define SMEM_ELT(base, r, seg, lc) \
    ((base) + (r) * ROW_BYTES + (((seg) ^ ((r) & 7)) << 4) + (lc) * 4)

__global__ void __launch_bounds__(THREADS)
lstm_mma_kernel(const float* __restrict__ x,  const float* __restrict__ h0,
                const float* __restrict__ c0, const float* __restrict__ Wx,
                const float* __restrict__ bx, const float* __restrict__ Wh,
                const float* __restrict__ bh, float* __restrict__ out)
{
    extern __shared__ __align__(128) char smem[];

    const int tid  = threadIdx.x;
    const int wid  = tid >> 5;
    const int lane = tid & 31;
    const int wm   = wid & 3;            // warp M index (0..3)
    const int wh   = wid >> 2;           // warp H index (0..1)
    const int lr   = lane >> 2;          // fragment row within 8 (0..7)
    const int lc   = lane & 3;           // fragment col within 4 (0..3)
    const int hblk = blockIdx.x * BH;
    const int mblk = blockIdx.y * BM;

    float acc[2][8][4];
    #pragma unroll
    for (int mt = 0; mt < 2; ++mt)
        #pragma unroll
        for (int nt = 0; nt < 8; ++nt)
            #pragma unroll
            for (int j = 0; j < 4; ++j)
                acc[mt][nt][j] = 0.0f;

    // ------- tile loader: chunk c into stage s -------
    auto load_chunk = [&](int c, int s) {
        const float* Asrc = (c < 16) ? x  : h0;
        const float* Wsrc = (c < 16) ? Wx : Wh;
        const int kg = (c & 15) * BK;
        const char* stg = smem + s * STAGE_BYTES;
        #pragma unroll
        for (int i = 0; i < 4; ++i) {
            int lin = tid + 256 * i;              // 0..1023
            int row = lin >> 3;                   // 0..127
            int seg = lin & 7;                    // 16B segment
            uint32_t so = (uint32_t)(row * ROW_BYTES + ((seg ^ (row & 7)) << 4));
            // A tile
            const float* ga = Asrc + (size_t)(mblk + row) * K_DIM + kg + seg * 4;
            CP16(s2u(stg + A_OFF) + so, ga);
            // B tile: row = gate*32 + local h
            int g = row >> 5, jn = row & 31;
            const float* gb = Wsrc + ((size_t)g * H_DIM + hblk + jn) * K_DIM + kg + seg * 4;
            CP16(s2u(stg + B_OFF) + so, gb);
        }
        CP_COMMIT();
    };

    // prologue: prefetch 2 chunks
    load_chunk(0, 0);
    load_chunk(1, 1);

    for (int c = 0; c < NCHUNKS; ++c) {
        __syncthreads();                          // stage (c+2)%3 now safe to overwrite
        if (c + 2 < NCHUNKS) load_chunk(c + 2, (c + 2) % STAGES);
        else CP_COMMIT();
        CP_WAIT2();
        __syncthreads();                          // chunk c visible to all

        const char* sa = smem + (c % STAGES) * STAGE_BYTES + A_OFF;
        const char* sb = smem + (c % STAGES) * STAGE_BYTES + B_OFF;

        #pragma unroll
        for (int ks = 0; ks < 4; ++ks) {
            const int seg0 = 2 * ks, seg1 = 2 * ks + 1;

            uint32_t a[2][4];
            #pragma unroll
            for (int mt = 0; mt < 2; ++mt) {
                int r0 = wm * 32 + mt * 16 + lr;
                int r1 = r0 + 8;
                a[mt][0] = f2tf32(*(const float*)SMEM_ELT(sa, r0, seg0, lc));
                a[mt][1] = f2tf32(*(const float*)SMEM_ELT(sa, r1, seg0, lc));
                a[mt][2] = f2tf32(*(const float*)SMEM_ELT(sa, r0, seg1, lc));
                a[mt][3] = f2tf32(*(const float*)SMEM_ELT(sa, r1, seg1, lc));
            }
            uint32_t b[8][2];
            #pragma unroll
            for (int nt = 0; nt < 8; ++nt) {
                int rn = (nt >> 1) * 32 + wh * 16 + (nt & 1) * 8 + lr;
                b[nt][0] = f2tf32(*(const float*)SMEM_ELT(sb, rn, seg0, lc));
                b[nt][1] = f2tf32(*(const float*)SMEM_ELT(sb, rn, seg1, lc));
            }
            #pragma unroll
            for (int mt = 0; mt < 2; ++mt)
                #pragma unroll
                for (int nt = 0; nt < 8; ++nt)
                    mma_tf32(acc[mt][nt], a[mt], b[nt]);
        }
    }

    // ------- fused LSTM epilogue (register-level gate fusion) -------
    // acc[mt][g*2+nh][rp*2+j] maps to:
    //   row = mblk + wm*32 + mt*16 + lr + rp*8
    //   h   = hblk + wh*16 + nh*8 + 2*lc + j     (gate = g)
    float2 bsum[8];
    #pragma unroll
    for (int nt = 0; nt < 8; ++nt) {
        int g = nt >> 1;
        int h = hblk + wh * 16 + (nt & 1) * 8 + 2 * lc;
        float2 vx = *(const float2*)(bx + (size_t)g * H_DIM + h);
        float2 vh = *(const float2*)(bh + (size_t)g * H_DIM + h);
        bsum[nt].x = vx.x + vh.x;
        bsum[nt].y = vx.y + vh.y;
    }

    #pragma unroll
    for (int mt = 0; mt < 2; ++mt) {
        #pragma unroll
        for (int rp = 0; rp < 2; ++rp) {
            const size_t r = (size_t)(mblk + wm * 32 + mt * 16 + lr + rp * 8);
            #pragma unroll
            for (int nh = 0; nh < 2; ++nh) {
                const int h = hblk + wh * 16 + nh * 8 + 2 * lc;
                float2 c0v = *(const float2*)(c0 + r * H_DIM + h);
                float2 hv, cv;
                #pragma unroll
                for (int j = 0; j < 2; ++j) {
                    float zi = acc[mt][0 + nh][rp * 2 + j] + (j ? bsum[0 + nh].y : bsum[0 + nh].x);
                    float zf = acc[mt][2 + nh][rp * 2 + j] + (j ? bsum[2 + nh].y : bsum[2 + nh].x);
                    float zo = acc[mt][4 + nh][rp * 2 + j] + (j ? bsum[4 + nh].y : bsum[4 + nh].x);
                    float zg = acc[mt][6 + nh][rp * 2 + j] + (j ? bsum[6 + nh].y : bsum[6 + nh].x);
                    float ig = 1.0f / (1.0f + expf(-zi));
                    float fg = 1.0f / (1.0f + expf(-zf));
                    float og = 1.0f / (1.0f + expf(-zo));
                    float gg = tanhf(zg);
                    float c1 = fg * (j ? c0v.y : c0v.x) + ig * gg;
                    float h1 = og * tanhf(c1);
                    if (j) { hv.y = h1; cv.y = c1; } else { hv.x = h1; cv.x = c1; }
                }
                *(float2*)(out + r * H_DIM + h) = hv;
                *(float2*)(out + (size_t)B_DIM * H_DIM + r * H_DIM + h) = cv;
            }
        }
    }
}

extern "C" void kernel_launch(void* const* d_in, const int* in_sizes, int n_in,
                              void* d_out, int out_size)
{
    const float* x  = (const float*)d_in[0];
    const float* h0 = (const float*)d_in[1];
    const float* c0 = (const float*)d_in[2];
    const float* Wx = (const float*)d_in[3];
    const float* bx = (const float*)d_in[4];
    const float* Wh = (const float*)d_in[5];
    const float* bh = (const float*)d_in[6];
    float* out = (float*)d_out;

    cudaFuncSetAttribute(lstm_mma_kernel,
                         cudaFuncAttributeMaxDynamicSharedMemorySize, SMEM_DYN);

    dim3 grid(H_DIM / BH, B_DIM / BM);   // (16, 256)
    lstm_mma_kernel<<<grid, THREADS, SMEM_DYN>>>(x, h0, c0, Wx, bx, Wh, bh, out);
}

// round 16
// speedup vs baseline: 4.1357x; 1.1962x over previous
#include <cuda_runtime.h>
#include <cstdint>
#include <math.h>

// LSTM cell via mma.sync m16n8k8 tf32 (plain sm_103-safe PTX).
// Z[M=32768, N=2048] = A[M,1024] * W[2048,1024]^T (NT, K-major both).
// K chunks [0,16): (x, Wx); [16,32): (h0, Wh).
// CTA tile 128(M) x 128(N = 4 gates x 32 h), BK=32, 3-stage cp.async.
// Raw fp32 bits fed to tf32 MMA (HW truncates mantissa) -> no cvt in mainloop.

#define B_DIM 32768
#define K_DIM 512
#define H_DIM 512

#define BM 128
#define BH 32
#define BK 32
#define STAGES 3
#define THREADS 256
#define NCHUNKS 32

#define ROW_BYTES 128                         // 32 floats per K-major row
#define A_OFF 0
#define B_OFF (BM * ROW_BYTES)                // 16 KB
#define STAGE_BYTES (2 * BM * ROW_BYTES)      // 32 KB
#define SMEM_DYN (STAGES * STAGE_BYTES)       // 96 KB

__device__ __forceinline__ uint32_t s2u(const void* p) {
    uint32_t a;
    asm("{ .reg .u64 t; cvta.to.shared.u64 t, %1; cvt.u32.u64 %0, t; }"
        : "=r"(a) : "l"(p));
    return a;
}

__device__ __forceinline__ void mma_tf32(float* c, const uint32_t* a, const uint32_t* b) {
    asm volatile(
        "mma.sync.aligned.m16n8k8.row.col.f32.tf32.tf32.f32 "
        "{%0,%1,%2,%3}, {%4,%5,%6,%7}, {%8,%9}, {%0,%1,%2,%3};"
        : "+f"(c[0]), "+f"(c[1]), "+f"(c[2]), "+f"(c[3])
        : "r"(a[0]), "r"(a[1]), "r"(a[2]), "r"(a[3]), "r"(b[0]), "r"(b[1]));
}

#define CP16(saddr, gaddr) \
    asm volatile("cp.async.cg.shared.global [%0], [%1], 16;" :: "r"(saddr), "l"(gaddr))
#define CP_COMMIT() asm volatile("cp.async.commit_group;" ::: "memory")
#define CP_WAIT1()  asm volatile("cp.async.wait_group 1;" ::: "memory")

// smem element: row-major [row][32 floats], 16B segments XOR-swizzled by row
#define SMEM_ELT(base, r, seg, lc) \
    ((base) + (r) * ROW_BYTES + (((seg) ^ ((r) & 7)) << 4) + (lc) * 4)

__global__ void __launch_bounds__(THREADS)
lstm_mma_kernel(const float* __restrict__ x,  const float* __restrict__ h0,
                const float* __restrict__ c0, const float* __restrict__ Wx,
                const float* __restrict__ bx, const float* __restrict__ Wh,
                const float* __restrict__ bh, float* __restrict__ out)
{
    extern __shared__ __align__(128) char smem[];

    const int tid  = threadIdx.x;
    const int wid  = tid >> 5;
    const int lane = tid & 31;
    const int wm   = wid & 3;            // warp M index (0..3)
    const int wh   = wid >> 2;           // warp H index (0..1)
    const int lr   = lane >> 2;          // fragment row (0..7)
    const int lc   = lane & 3;           // fragment col (0..3)
    const int hblk = blockIdx.x * BH;
    const int mblk = blockIdx.y * BM;

    float acc[2][8][4];
    #pragma unroll
    for (int mt = 0; mt < 2; ++mt)
        #pragma unroll
        for (int nt = 0; nt < 8; ++nt)
            #pragma unroll
            for (int j = 0; j < 4; ++j)
                acc[mt][nt][j] = 0.0f;

    auto load_chunk = [&](int c, int s) {
        const float* Asrc = (c < 16) ? x  : h0;
        const float* Wsrc = (c < 16) ? Wx : Wh;
        const int kg = (c & 15) * BK;
        const char* stg = smem + s * STAGE_BYTES;
        #pragma unroll
        for (int i = 0; i < 4; ++i) {
            int lin = tid + 256 * i;              // 0..1023
            int row = lin >> 3;                   // 0..127
            int seg = lin & 7;
            uint32_t so = (uint32_t)(row * ROW_BYTES + ((seg ^ (row & 7)) << 4));
            const float* ga = Asrc + (size_t)(mblk + row) * K_DIM + kg + seg * 4;
            CP16(s2u(stg + A_OFF) + so, ga);
            int g = row >> 5, jn = row & 31;
            const float* gb = Wsrc + ((size_t)g * H_DIM + hblk + jn) * K_DIM + kg + seg * 4;
            CP16(s2u(stg + B_OFF) + so, gb);
        }
        CP_COMMIT();
    };

    // prologue: 2 chunks in flight
    load_chunk(0, 0);
    load_chunk(1, 1);

    for (int c = 0; c < NCHUNKS; ++c) {
        CP_WAIT1();            // chunk c complete (c+1 still in flight)
        __syncthreads();       // publish chunk c; all warps done with chunk c-1
        if (c + 2 < NCHUNKS) load_chunk(c + 2, (c + 2) % STAGES);
        else CP_COMMIT();      // keep group count uniform

        const char* sa = smem + (c % STAGES) * STAGE_BYTES + A_OFF;
        const char* sb = smem + (c % STAGES) * STAGE_BYTES + B_OFF;

        #pragma unroll
        for (int ks = 0; ks < 4; ++ks) {
            const int seg0 = 2 * ks, seg1 = 2 * ks + 1;

            uint32_t a[2][4];
            #pragma unroll
            for (int mt = 0; mt < 2; ++mt) {
                int r0 = wm * 32 + mt * 16 + lr;
                int r1 = r0 + 8;
                a[mt][0] = *(const uint32_t*)SMEM_ELT(sa, r0, seg0, lc);
                a[mt][1] = *(const uint32_t*)SMEM_ELT(sa, r1, seg0, lc);
                a[mt][2] = *(const uint32_t*)SMEM_ELT(sa, r0, seg1, lc);
                a[mt][3] = *(const uint32_t*)SMEM_ELT(sa, r1, seg1, lc);
            }
            uint32_t b[8][2];
            #pragma unroll
            for (int nt = 0; nt < 8; ++nt) {
                int rn = (nt >> 1) * 32 + wh * 16 + (nt & 1) * 8 + lr;
                b[nt][0] = *(const uint32_t*)SMEM_ELT(sb, rn, seg0, lc);
                b[nt][1] = *(const uint32_t*)SMEM_ELT(sb, rn, seg1, lc);
            }
            #pragma unroll
            for (int mt = 0; mt < 2; ++mt)
                #pragma unroll
                for (int nt = 0; nt < 8; ++nt)
                    mma_tf32(acc[mt][nt], a[mt], b[nt]);
        }
    }

    // ------- fused LSTM epilogue (register-level gate fusion) -------
    float2 bsum[8];
    #pragma unroll
    for (int nt = 0; nt < 8; ++nt) {
        int g = nt >> 1;
        int h = hblk + wh * 16 + (nt & 1) * 8 + 2 * lc;
        float2 vx = *(const float2*)(bx + (size_t)g * H_DIM + h);
        float2 vh = *(const float2*)(bh + (size_t)g * H_DIM + h);
        bsum[nt].x = vx.x + vh.x;
        bsum[nt].y = vx.y + vh.y;
    }

    #pragma unroll
    for (int mt = 0; mt < 2; ++mt) {
        #pragma unroll
        for (int rp = 0; rp < 2; ++rp) {
            const size_t r = (size_t)(mblk + wm * 32 + mt * 16 + lr + rp * 8);
            #pragma unroll
            for (int nh = 0; nh < 2; ++nh) {
                const int h = hblk + wh * 16 + nh * 8 + 2 * lc;
                float2 c0v = *(const float2*)(c0 + r * H_DIM + h);
                float2 hv, cv;
                #pragma unroll
                for (int j = 0; j < 2; ++j) {
                    float zi = acc[mt][0 + nh][rp * 2 + j] + (j ? bsum[0 + nh].y : bsum[0 + nh].x);
                    float zf = acc[mt][2 + nh][rp * 2 + j] + (j ? bsum[2 + nh].y : bsum[2 + nh].x);
                    float zo = acc[mt][4 + nh][rp * 2 + j] + (j ? bsum[4 + nh].y : bsum[4 + nh].x);
                    float zg = acc[mt][6 + nh][rp * 2 + j] + (j ? bsum[6 + nh].y : bsum[6 + nh].x);
                    float ig = 1.0f / (1.0f + expf(-zi));
                    float fg = 1.0f / (1.0f + expf(-zf));
                    float og = 1.0f / (1.0f + expf(-zo));
                    float gg = tanhf(zg);
                    float c1 = fg * (j ? c0v.y : c0v.x) + ig * gg;
                    float h1 = og * tanhf(c1);
                    if (j) { hv.y = h1; cv.y = c1; } else { hv.x = h1; cv.x = c1; }
                }
                *(float2*)(out + r * H_DIM + h) = hv;
                *(float2*)(out + (size_t)B_DIM * H_DIM + r * H_DIM + h) = cv;
            }
        }
    }
}

extern "C" void kernel_launch(void* const* d_in, const int* in_sizes, int n_in,
                              void* d_out, int out_size)
{
    const float* x  = (const float*)d_in[0];
    const float* h0 = (const float*)d_in[1];
    const float* c0 = (const float*)d_in[2];
    const float* Wx = (const float*)d_in[3];
    const float* bx = (const float*)d_in[4];
    const float* Wh = (const float*)d_in[5];
    const float* bh = (const float*)d_in[6];
    float* out = (float*)d_out;

    cudaFuncSetAttribute(lstm_mma_kernel,
                         cudaFuncAttributeMaxDynamicSharedMemorySize, SMEM_DYN);

    dim3 grid(H_DIM / BH, B_DIM / BM);   // (16, 256)
    lstm_mma_kernel<<<grid, THREADS, SMEM_DYN>>>(x, h0, c0, Wx, bx, Wh, bh, out);
}